// round 9
// baseline (speedup 1.0000x reference)
#include <cuda_runtime.h>
#include <cuda_bf16.h>
#include <cstdint>

#define BATCH 4
#define CH    256
#define SP    4096
#define DH    256

__device__ __align__(16) __nv_bfloat16 g_qh[BATCH * CH * SP];
__device__ __align__(16) __nv_bfloat16 g_ql[BATCH * CH * SP];
__device__ __align__(16) __nv_bfloat16 g_kh[BATCH * CH * SP];
__device__ __align__(16) __nv_bfloat16 g_kl[BATCH * CH * SP];
__device__ __align__(16) __nv_bfloat16 g_vh[BATCH * CH * SP];
__device__ __align__(16) __nv_bfloat16 g_vl[BATCH * CH * SP];
__device__ __align__(16) float g_a[BATCH * CH * SP];

// ---------------- helpers ----------------
__device__ __forceinline__ uint32_t pk(float x0, float x1) {
    uint32_t r;
    asm("cvt.rn.bf16x2.f32 %0, %1, %2;" : "=r"(r) : "f"(x1), "f"(x0));
    return r;
}
__device__ __forceinline__ void split2(float x0, float x1, uint32_t& hi, uint32_t& lo) {
    float h0 = __bfloat162float(__float2bfloat16(x0));
    float h1 = __bfloat162float(__float2bfloat16(x1));
    hi = pk(x0, x1);
    lo = pk(x0 - h0, x1 - h1);
}
__device__ __forceinline__ void ldsm4(uint32_t* r, uint32_t a) {
    asm volatile("ldmatrix.sync.aligned.m8n8.x4.shared.b16 {%0,%1,%2,%3}, [%4];"
                 : "=r"(r[0]), "=r"(r[1]), "=r"(r[2]), "=r"(r[3]) : "r"(a));
}
__device__ __forceinline__ void ldsm4t(uint32_t* r, uint32_t a) {
    asm volatile("ldmatrix.sync.aligned.m8n8.x4.trans.shared.b16 {%0,%1,%2,%3}, [%4];"
                 : "=r"(r[0]), "=r"(r[1]), "=r"(r[2]), "=r"(r[3]) : "r"(a));
}
__device__ __forceinline__ void mma16816(float* d, const uint32_t* a, uint32_t b0, uint32_t b1) {
    asm volatile("mma.sync.aligned.m16n8k16.row.col.f32.bf16.bf16.f32 "
                 "{%0,%1,%2,%3}, {%4,%5,%6,%7}, {%8,%9}, {%0,%1,%2,%3};"
                 : "+f"(d[0]), "+f"(d[1]), "+f"(d[2]), "+f"(d[3])
                 : "r"(a[0]), "r"(a[1]), "r"(a[2]), "r"(a[3]), "r"(b0), "r"(b1));
}
__device__ __forceinline__ uint32_t sm_u32(const void* p) {
    return (uint32_t)__cvta_generic_to_shared(p);
}
__device__ __forceinline__ void cpa16(uint32_t dst, const void* src) {
    asm volatile("cp.async.cg.shared.global [%0], [%1], 16;" :: "r"(dst), "l"(src));
}
__device__ __forceinline__ void cpa_commit() { asm volatile("cp.async.commit_group;"); }
__device__ __forceinline__ void cpa_wait_all() { asm volatile("cp.async.wait_group 0;"); }
__device__ __forceinline__ void sts32(uint32_t a, uint32_t v) {
    asm volatile("st.shared.b32 [%0], %1;" :: "r"(a), "r"(v) : "memory");
}
#define BARP(id) asm volatile("bar.sync %0, 64;" :: "r"(id) : "memory")

// ---------------------------------------------------------------------------
// Kernel 1: fused Q/K/V 1x1 conv -> bf16 hi/lo
// ---------------------------------------------------------------------------
__global__ __launch_bounds__(256) void qkv_kernel(
    const float* __restrict__ x,
    const float* __restrict__ Wq, const float* __restrict__ bq,
    const float* __restrict__ Wk, const float* __restrict__ bk,
    const float* __restrict__ Wv, const float* __restrict__ bv)
{
    __shared__ float Ws[16][68];
    __shared__ float Xs[16][128];
    int z = blockIdx.z, b = z / 3, w = z % 3;
    const float* W    = (w == 0) ? Wq : (w == 1) ? Wk : Wv;
    const float* bias = (w == 0) ? bq : (w == 1) ? bk : bv;
    __nv_bfloat16* outh = (w == 0) ? g_qh : (w == 1) ? g_kh : g_vh;
    __nv_bfloat16* outl = (w == 0) ? g_ql : (w == 1) ? g_kl : g_vl;
    int m0 = blockIdx.y * 64, s0 = blockIdx.x * 128;
    int tid = threadIdx.x, ty = tid >> 4, tx = tid & 15;
    float acc[4][8];
#pragma unroll
    for (int i = 0; i < 4; i++)
#pragma unroll
        for (int j = 0; j < 8; j++) acc[i][j] = 0.0f;
    const float* xb = x + (size_t)b * CH * SP;
    for (int k0 = 0; k0 < CH; k0 += 16) {
        {
            int mm = tid & 63, kk4 = (tid >> 6) << 2;
            float4 wv = *(const float4*)&W[(m0 + mm) * CH + k0 + kk4];
            Ws[kk4 + 0][mm] = wv.x; Ws[kk4 + 1][mm] = wv.y;
            Ws[kk4 + 2][mm] = wv.z; Ws[kk4 + 3][mm] = wv.w;
        }
        {
            int kk = tid >> 4, nn = (tid & 15) * 8;
            const float* xp = xb + (size_t)(k0 + kk) * SP + s0 + nn;
            *(float4*)&Xs[kk][nn]     = *(const float4*)xp;
            *(float4*)&Xs[kk][nn + 4] = *(const float4*)(xp + 4);
        }
        __syncthreads();
#pragma unroll
        for (int k = 0; k < 16; k++) {
            float4 a  = *(const float4*)&Ws[k][ty * 4];
            float4 b0 = *(const float4*)&Xs[k][tx * 8];
            float4 b1 = *(const float4*)&Xs[k][tx * 8 + 4];
            float av[4] = {a.x, a.y, a.z, a.w};
            float bw[8] = {b0.x, b0.y, b0.z, b0.w, b1.x, b1.y, b1.z, b1.w};
#pragma unroll
            for (int i = 0; i < 4; i++)
#pragma unroll
                for (int j = 0; j < 8; j++) acc[i][j] = fmaf(av[i], bw[j], acc[i][j]);
        }
        __syncthreads();
    }
    size_t ob = (size_t)b * CH * SP;
#pragma unroll
    for (int i = 0; i < 4; i++) {
        int m = m0 + ty * 4 + i;
        float bi = bias[m];
        float v[8];
#pragma unroll
        for (int j = 0; j < 8; j++) v[j] = acc[i][j] + bi;
        uint4 hw, lw;
        split2(v[0], v[1], hw.x, lw.x); split2(v[2], v[3], hw.y, lw.y);
        split2(v[4], v[5], hw.z, lw.z); split2(v[6], v[7], hw.w, lw.w);
        size_t off = ob + (size_t)m * SP + s0 + tx * 8;
        *(uint4*)&outh[off] = hw;
        *(uint4*)&outl[off] = lw;
    }
}

// ---------------------------------------------------------------------------
// Kernel 2: flash attention, mma.sync, 512 threads = 16 warps (pair-split).
// Pair p (warps 2p, 2p+1) owns Q rows 16p..16p+15.
//  - S phase: warp h computes keys 16h..16h+15 (half)
//  - PV phase: warp h computes O cols 128h..128h+127 (half)
// Cross-warp: row max/sum partials + P fragments via smem + named barriers.
// ---------------------------------------------------------------------------
#define SQ 264
// byte offsets within dynamic smem
#define PS_B   202752              // 16 x (512B hi + 512B lo) = 16384 B
#define REDM_B 219136              // 256 floats
#define REDS_B 220160              // 256 floats
#define ATTN_SMEM 221184

__global__ __launch_bounds__(512, 1) void attn_kernel()
{
    extern __shared__ __nv_bfloat16 sm[];
    __nv_bfloat16* Qh = sm;
    __nv_bfloat16* Ql = Qh + 128 * SQ;
    __nv_bfloat16* Kh = Ql + 128 * SQ;
    __nv_bfloat16* Kl = Kh + 32 * SQ;
    __nv_bfloat16* Vh = Kl + 32 * SQ;
    __nv_bfloat16* Vl = Vh + 32 * SQ;
    uint32_t smb = sm_u32(sm);
    float* redM = (float*)((char*)sm + REDM_B);
    float* redS = (float*)((char*)sm + REDS_B);

    int b = blockIdx.y, n0 = blockIdx.x * 128;
    int tid = threadIdx.x;
    int w = tid >> 5, lane = tid & 31;
    int p = w >> 1, h = w & 1;

    size_t base = (size_t)b * CH * SP;
    const uint4* Qgh = (const uint4*)(g_qh + base);
    const uint4* Qgl = (const uint4*)(g_ql + base);
    const uint4* Kgh = (const uint4*)(g_kh + base);
    const uint4* Kgl = (const uint4*)(g_kl + base);
    const uint4* Vgh = (const uint4*)(g_vh + base);
    const uint4* Vgl = (const uint4*)(g_vl + base);

    // cp.async slots: 32-row tile = 1024 uint4 per buffer; 512 thr -> 2 each
    int lr = tid >> 4;            // 0..31
    int lc = (tid & 15) * 2;      // 0..30
    uint32_t sKh = sm_u32(Kh), sKl = sm_u32(Kl), sVh = sm_u32(Vh), sVl = sm_u32(Vl);

    // issue K_0
    {
        size_t g = (size_t)lr * 32 + lc;
#pragma unroll
        for (int j = 0; j < 2; j++) {
            uint32_t so = (uint32_t)(lr * 33 + lc + j) * 16;
            cpa16(sKh + so, Kgh + g + j);
            cpa16(sKl + so, Kgl + g + j);
        }
        cpa_commit();
    }

    // load Q tile (128 x 256, hi+lo)
    for (int idx = tid; idx < 128 * 32; idx += 512) {
        int r = idx >> 5, c = idx & 31;
        ((uint4*)Qh)[r * 33 + c] = Qgh[(size_t)(n0 + r) * 32 + c];
        ((uint4*)Ql)[r * 33 + c] = Qgl[(size_t)(n0 + r) * 32 + c];
    }

    // ldmatrix addresses
    int rsel = lane & 15, csel = lane >> 4;
    uint32_t aQh = sm_u32(Qh + (p * 16 + rsel) * SQ + csel * 8);
    uint32_t aQl = aQh + 128 * SQ * 2;
    uint32_t aKh = sm_u32(Kh + (h * 16 + rsel) * SQ + csel * 8);
    uint32_t aKl = aKh + 32 * SQ * 2;
    uint32_t aVh = sm_u32(Vh + rsel * SQ + csel * 8);
    uint32_t aVl = aVh + 32 * SQ * 2;
    uint32_t psOwn  = smb + PS_B + (uint32_t)(p * 2 + h) * 1024;
    uint32_t psPart = smb + PS_B + (uint32_t)(p * 2 + (1 - h)) * 1024;
    uint32_t psLd   = psPart + rsel * 32 + csel * 16;

    int r0v = lane >> 2;
    int c2 = (lane & 3) * 2;
    int ridx  = (p * 2 + h) * 16 + r0v;
    int ridxO = (p * 2 + (1 - h)) * 16 + r0v;

    float o[16][4];
#pragma unroll
    for (int i = 0; i < 16; i++)
#pragma unroll
        for (int j = 0; j < 4; j++) o[i][j] = 0.0f;
    float m0 = -1e30f, m1 = -1e30f, l0 = 0.0f, l1 = 0.0f;

    for (int t = 0; t < 128; t++) {
        cpa_wait_all();
        __syncthreads();

        // issue V_t
        {
            size_t g = (size_t)(t * 32 + lr) * 32 + lc;
#pragma unroll
            for (int j = 0; j < 2; j++) {
                uint32_t so = (uint32_t)(lr * 33 + lc + j) * 16;
                cpa16(sVh + so, Vgh + g + j);
                cpa16(sVl + so, Vgl + g + j);
            }
            cpa_commit();
        }

        // ---- S: 16 rows (pair) x 16 keys (this warp's half) ----
        float s0[4] = {0, 0, 0, 0}, s1[4] = {0, 0, 0, 0};
#pragma unroll
        for (int kc = 0; kc < 16; kc++) {
            uint32_t ah[4], al[4], bh[4], bl[4];
            ldsm4(ah, aQh + kc * 32);
            ldsm4(al, aQl + kc * 32);
            ldsm4(bh, aKh + kc * 32);
            ldsm4(bl, aKl + kc * 32);
            mma16816(s0, ah, bh[0], bh[2]);
            mma16816(s0, ah, bl[0], bl[2]);
            mma16816(s0, al, bh[0], bh[2]);
            mma16816(s1, ah, bh[1], bh[3]);
            mma16816(s1, ah, bl[1], bl[3]);
            mma16816(s1, al, bh[1], bh[3]);
        }

        cpa_wait_all();
        __syncthreads();

        // issue K_{t+1}
        if (t + 1 < 128) {
            size_t g = (size_t)((t + 1) * 32 + lr) * 32 + lc;
#pragma unroll
            for (int j = 0; j < 2; j++) {
                uint32_t so = (uint32_t)(lr * 33 + lc + j) * 16;
                cpa16(sKh + so, Kgh + g + j);
                cpa16(sKl + so, Kgl + g + j);
            }
            cpa_commit();
        }

        // ---- softmax with pair-combine ----
        float mx0 = fmaxf(fmaxf(s0[0], s0[1]), fmaxf(s1[0], s1[1]));
        float mx1 = fmaxf(fmaxf(s0[2], s0[3]), fmaxf(s1[2], s1[3]));
        mx0 = fmaxf(mx0, __shfl_xor_sync(0xffffffffu, mx0, 1));
        mx0 = fmaxf(mx0, __shfl_xor_sync(0xffffffffu, mx0, 2));
        mx1 = fmaxf(mx1, __shfl_xor_sync(0xffffffffu, mx1, 1));
        mx1 = fmaxf(mx1, __shfl_xor_sync(0xffffffffu, mx1, 2));
        if ((lane & 3) == 0) {
            redM[ridx] = mx0;
            redM[ridx + 8] = mx1;
        }
        BARP(p + 1);
        mx0 = fmaxf(mx0, redM[ridxO]);
        mx1 = fmaxf(mx1, redM[ridxO + 8]);

        float mn0 = fmaxf(m0, mx0), mn1 = fmaxf(m1, mx1);
        float sc0 = __expf(m0 - mn0), sc1 = __expf(m1 - mn1);
        m0 = mn0; m1 = mn1;

        s0[0] = __expf(s0[0] - mn0); s0[1] = __expf(s0[1] - mn0);
        s1[0] = __expf(s1[0] - mn0); s1[1] = __expf(s1[1] - mn0);
        s0[2] = __expf(s0[2] - mn1); s0[3] = __expf(s0[3] - mn1);
        s1[2] = __expf(s1[2] - mn1); s1[3] = __expf(s1[3] - mn1);
        float rs0 = s0[0] + s0[1] + s1[0] + s1[1];
        float rs1 = s0[2] + s0[3] + s1[2] + s1[3];
        rs0 += __shfl_xor_sync(0xffffffffu, rs0, 1);
        rs0 += __shfl_xor_sync(0xffffffffu, rs0, 2);
        rs1 += __shfl_xor_sync(0xffffffffu, rs1, 1);
        rs1 += __shfl_xor_sync(0xffffffffu, rs1, 2);
        if ((lane & 3) == 0) {
            redS[ridx] = rs0;
            redS[ridx + 8] = rs1;
        }

        // pack P (own half) as A-fragment + store for partner
        uint32_t Ph[2][4], Pl[2][4];
        split2(s0[0], s0[1], Ph[h][0], Pl[h][0]);
        split2(s0[2], s0[3], Ph[h][1], Pl[h][1]);
        split2(s1[0], s1[1], Ph[h][2], Pl[h][2]);
        split2(s1[2], s1[3], Ph[h][3], Pl[h][3]);
        {
            uint32_t ad = psOwn + (uint32_t)(r0v * 32 + c2 * 2);
            sts32(ad,             Ph[h][0]);
            sts32(ad + 256,       Ph[h][1]);
            sts32(ad + 16,        Ph[h][2]);
            sts32(ad + 272,       Ph[h][3]);
            sts32(ad + 512,       Pl[h][0]);
            sts32(ad + 768,       Pl[h][1]);
            sts32(ad + 528,       Pl[h][2]);
            sts32(ad + 784,       Pl[h][3]);
        }
        BARP(p + 1);

        float os0 = redS[ridxO], os1 = redS[ridxO + 8];
        l0 = l0 * sc0 + rs0 + os0;
        l1 = l1 * sc1 + rs1 + os1;

#pragma unroll
        for (int nt = 0; nt < 16; nt++) {
            o[nt][0] *= sc0; o[nt][1] *= sc0;
            o[nt][2] *= sc1; o[nt][3] *= sc1;
        }

        // partner's P fragments (other key half)
        ldsm4(Ph[1 - h], psLd);
        ldsm4(Pl[1 - h], psLd + 512);

        // ---- PV: O[16 rows x 128 cols (this half)] += P * V ----
#pragma unroll
        for (int kc = 0; kc < 2; kc++) {
#pragma unroll
            for (int ctp = 0; ctp < 8; ctp++) {
                int ct = 8 * h + ctp;
                uint32_t vh[4], vl[4];
                ldsm4t(vh, aVh + kc * (16 * SQ * 2) + ct * 32);
                ldsm4t(vl, aVl + kc * (16 * SQ * 2) + ct * 32);
                float* oA = o[2 * ctp];
                float* oB = o[2 * ctp + 1];
                mma16816(oA, Ph[kc], vh[0], vh[1]);
                mma16816(oA, Ph[kc], vl[0], vl[1]);
                mma16816(oA, Pl[kc], vh[0], vh[1]);
                mma16816(oB, Ph[kc], vh[2], vh[3]);
                mma16816(oB, Ph[kc], vl[2], vl[3]);
                mma16816(oB, Pl[kc], vh[2], vh[3]);
            }
        }
    }

    // ---- epilogue ----
    float inv0 = 1.0f / l0, inv1 = 1.0f / l1;
    int r0g = n0 + p * 16 + r0v;
    int r1g = r0g + 8;
    float* A = g_a + base;
#pragma unroll
    for (int nt = 0; nt < 16; nt++) {
        int c = 128 * h + nt * 8 + c2;
        float2 v0 = make_float2(o[nt][0] * inv0, o[nt][1] * inv0);
        float2 v1 = make_float2(o[nt][2] * inv1, o[nt][3] * inv1);
        *(float2*)&A[(size_t)r0g * 256 + c] = v0;
        *(float2*)&A[(size_t)r1g * 256 + c] = v1;
    }
}

// ---------------------------------------------------------------------------
// Kernel 3: out = x + Wu * attn + bu
// ---------------------------------------------------------------------------
__global__ __launch_bounds__(256) void out_kernel(
    const float* __restrict__ x, const float* __restrict__ Wu,
    const float* __restrict__ bu, float* __restrict__ out)
{
    __shared__ float Ws[16][68];
    __shared__ float Xs[16][128];
    int b = blockIdx.z, m0 = blockIdx.y * 64, s0 = blockIdx.x * 128;
    int tid = threadIdx.x, ty = tid >> 4, tx = tid & 15;
    float acc[4][8];
#pragma unroll
    for (int i = 0; i < 4; i++)
#pragma unroll
        for (int j = 0; j < 8; j++) acc[i][j] = 0.0f;
    const float* Ab = g_a + (size_t)b * CH * SP;
    for (int k0 = 0; k0 < CH; k0 += 16) {
        {
            int mm = tid & 63, kk4 = (tid >> 6) << 2;
            float4 wv = *(const float4*)&Wu[(m0 + mm) * CH + k0 + kk4];
            Ws[kk4 + 0][mm] = wv.x; Ws[kk4 + 1][mm] = wv.y;
            Ws[kk4 + 2][mm] = wv.z; Ws[kk4 + 3][mm] = wv.w;
        }
        {
            int kk = tid >> 4, nn = (tid & 15) * 8;
            const float* ap = Ab + (size_t)(k0 + kk) * SP + s0 + nn;
            *(float4*)&Xs[kk][nn]     = *(const float4*)ap;
            *(float4*)&Xs[kk][nn + 4] = *(const float4*)(ap + 4);
        }
        __syncthreads();
#pragma unroll
        for (int k = 0; k < 16; k++) {
            float4 a  = *(const float4*)&Ws[k][ty * 4];
            float4 b0 = *(const float4*)&Xs[k][tx * 8];
            float4 b1 = *(const float4*)&Xs[k][tx * 8 + 4];
            float av[4] = {a.x, a.y, a.z, a.w};
            float bw[8] = {b0.x, b0.y, b0.z, b0.w, b1.x, b1.y, b1.z, b1.w};
#pragma unroll
            for (int i = 0; i < 4; i++)
#pragma unroll
                for (int j = 0; j < 8; j++) acc[i][j] = fmaf(av[i], bw[j], acc[i][j]);
        }
        __syncthreads();
    }
#pragma unroll
    for (int i = 0; i < 4; i++) {
        int mm = m0 + ty * 4 + i;
        float bi = bu[mm];
        size_t bo = (size_t)b * CH * SP + (size_t)mm * SP + s0 + tx * 8;
        float4 x0 = *(const float4*)&x[bo];
        float4 x1 = *(const float4*)&x[bo + 4];
        float4 r0, r1;
        r0.x = acc[i][0] + bi + x0.x; r0.y = acc[i][1] + bi + x0.y;
        r0.z = acc[i][2] + bi + x0.z; r0.w = acc[i][3] + bi + x0.w;
        r1.x = acc[i][4] + bi + x1.x; r1.y = acc[i][5] + bi + x1.y;
        r1.z = acc[i][6] + bi + x1.z; r1.w = acc[i][7] + bi + x1.w;
        *(float4*)&out[bo]     = r0;
        *(float4*)&out[bo + 4] = r1;
    }
}

// ---------------------------------------------------------------------------
extern "C" void kernel_launch(void* const* d_in, const int* in_sizes, int n_in,
                              void* d_out, int out_size)
{
    (void)in_sizes; (void)n_in; (void)out_size;
    const float* x  = (const float*)d_in[0];
    const float* Wq = (const float*)d_in[1];
    const float* bq = (const float*)d_in[2];
    const float* Wk = (const float*)d_in[3];
    const float* bk = (const float*)d_in[4];
    const float* Wv = (const float*)d_in[5];
    const float* bv = (const float*)d_in[6];
    const float* Wu = (const float*)d_in[7];
    const float* bu = (const float*)d_in[8];
    float* out = (float*)d_out;

    cudaFuncSetAttribute(attn_kernel, cudaFuncAttributeMaxDynamicSharedMemorySize, ATTN_SMEM);

    qkv_kernel<<<dim3(32, 4, 12), 256>>>(x, Wq, bq, Wk, bk, Wv, bv);
    attn_kernel<<<dim3(32, 4), 512, ATTN_SMEM>>>();
    out_kernel<<<dim3(32, 4, 4), 256>>>(x, Wu, bu, out);
}

// round 10
// speedup vs baseline: 1.3333x; 1.3333x over previous
#include <cuda_runtime.h>
#include <cuda_bf16.h>
#include <cstdint>

#define BATCH 4
#define CH    256
#define SP    4096
#define DH    256

__device__ __align__(16) __nv_bfloat16 g_xh[BATCH * CH * SP];
__device__ __align__(16) __nv_bfloat16 g_xl[BATCH * CH * SP];
__device__ __align__(16) __nv_bfloat16 g_wh[4 * 65536];
__device__ __align__(16) __nv_bfloat16 g_wl[4 * 65536];
__device__ __align__(16) __nv_bfloat16 g_qh[BATCH * CH * SP];
__device__ __align__(16) __nv_bfloat16 g_ql[BATCH * CH * SP];
__device__ __align__(16) __nv_bfloat16 g_kh[BATCH * CH * SP];
__device__ __align__(16) __nv_bfloat16 g_kl[BATCH * CH * SP];
__device__ __align__(16) __nv_bfloat16 g_vh[BATCH * CH * SP];
__device__ __align__(16) __nv_bfloat16 g_vl[BATCH * CH * SP];
__device__ __align__(16) __nv_bfloat16 g_ah[BATCH * CH * SP];
__device__ __align__(16) __nv_bfloat16 g_al[BATCH * CH * SP];

// ---------------- helpers ----------------
__device__ __forceinline__ uint32_t pk(float x0, float x1) {
    uint32_t r;
    asm("cvt.rn.bf16x2.f32 %0, %1, %2;" : "=r"(r) : "f"(x1), "f"(x0));
    return r;
}
__device__ __forceinline__ void split2(float x0, float x1, uint32_t& hi, uint32_t& lo) {
    float h0 = __bfloat162float(__float2bfloat16(x0));
    float h1 = __bfloat162float(__float2bfloat16(x1));
    hi = pk(x0, x1);
    lo = pk(x0 - h0, x1 - h1);
}
__device__ __forceinline__ void ldsm4(uint32_t* r, uint32_t a) {
    asm volatile("ldmatrix.sync.aligned.m8n8.x4.shared.b16 {%0,%1,%2,%3}, [%4];"
                 : "=r"(r[0]), "=r"(r[1]), "=r"(r[2]), "=r"(r[3]) : "r"(a));
}
__device__ __forceinline__ void ldsm4t(uint32_t* r, uint32_t a) {
    asm volatile("ldmatrix.sync.aligned.m8n8.x4.trans.shared.b16 {%0,%1,%2,%3}, [%4];"
                 : "=r"(r[0]), "=r"(r[1]), "=r"(r[2]), "=r"(r[3]) : "r"(a));
}
__device__ __forceinline__ void mma16816(float* d, const uint32_t* a, uint32_t b0, uint32_t b1) {
    asm volatile("mma.sync.aligned.m16n8k16.row.col.f32.bf16.bf16.f32 "
                 "{%0,%1,%2,%3}, {%4,%5,%6,%7}, {%8,%9}, {%0,%1,%2,%3};"
                 : "+f"(d[0]), "+f"(d[1]), "+f"(d[2]), "+f"(d[3])
                 : "r"(a[0]), "r"(a[1]), "r"(a[2]), "r"(a[3]), "r"(b0), "r"(b1));
}
__device__ __forceinline__ uint32_t sm_u32(const void* p) {
    return (uint32_t)__cvta_generic_to_shared(p);
}
__device__ __forceinline__ void cpa16(uint32_t dst, const void* src) {
    asm volatile("cp.async.cg.shared.global [%0], [%1], 16;" :: "r"(dst), "l"(src));
}
__device__ __forceinline__ void cpa_commit() { asm volatile("cp.async.commit_group;"); }
__device__ __forceinline__ void cpa_wait_all() { asm volatile("cp.async.wait_group 0;"); }

// ---------------------------------------------------------------------------
// Split kernels: fp32 -> bf16 hi/lo
// ---------------------------------------------------------------------------
__global__ __launch_bounds__(256) void splitx_kernel(const float* __restrict__ x)
{
    size_t i = ((size_t)blockIdx.x * 256 + threadIdx.x) * 4;
    float4 v = *(const float4*)(x + i);
    uint32_t h0, l0, h1, l1;
    split2(v.x, v.y, h0, l0);
    split2(v.z, v.w, h1, l1);
    uint2 hw, lw;
    hw.x = h0; hw.y = h1; lw.x = l0; lw.y = l1;
    *(uint2*)&g_xh[i] = hw;
    *(uint2*)&g_xl[i] = lw;
}

__global__ __launch_bounds__(256) void splitw_kernel(
    const float* __restrict__ Wq, const float* __restrict__ Wk,
    const float* __restrict__ Wv, const float* __restrict__ Wu)
{
    size_t i = ((size_t)blockIdx.x * 256 + threadIdx.x) * 4;
    int which = (int)(i >> 16);
    const float* W = (which == 0) ? Wq : (which == 1) ? Wk : (which == 2) ? Wv : Wu;
    float4 v = *(const float4*)(W + (i & 65535));
    uint32_t h0, l0, h1, l1;
    split2(v.x, v.y, h0, l0);
    split2(v.z, v.w, h1, l1);
    uint2 hw, lw;
    hw.x = h0; hw.y = h1; lw.x = l0; lw.y = l1;
    *(uint2*)&g_wh[i] = hw;
    *(uint2*)&g_wl[i] = lw;
}

// ---------------------------------------------------------------------------
// Conv GEMM on tensor cores (bf16 hi/lo, 3-term). CTA: 128(out-ch) x 128(sp).
// smem per stage: Wh[128][24] Wl Xh[16][136] Xl; double buffered.
// ---------------------------------------------------------------------------
#define STG 21504
#define WL_OFF 6144
#define XH_OFF 12288
#define XL_OFF 16640

__device__ __forceinline__ void conv_issue(
    uint32_t sb, int tid, int kc,
    const __nv_bfloat16* gwh, const __nv_bfloat16* gwl,
    const __nv_bfloat16* xh, const __nv_bfloat16* xl,
    int m0, int s0)
{
    int mm = tid & 127, g = tid >> 7;
    const __nv_bfloat16* swh = gwh + (size_t)(m0 + mm) * 256 + kc * 16 + g * 8;
    const __nv_bfloat16* swl = gwl + (size_t)(m0 + mm) * 256 + kc * 16 + g * 8;
    cpa16(sb + mm * 48 + g * 16, swh);
    cpa16(sb + WL_OFF + mm * 48 + g * 16, swl);
    int kk = tid >> 4, sg = (tid & 15) * 8;
    const __nv_bfloat16* sxh = xh + (size_t)(kc * 16 + kk) * SP + s0 + sg;
    const __nv_bfloat16* sxl = xl + (size_t)(kc * 16 + kk) * SP + s0 + sg;
    cpa16(sb + XH_OFF + kk * 272 + sg * 2, sxh);
    cpa16(sb + XL_OFF + kk * 272 + sg * 2, sxl);
}

__device__ __forceinline__ void conv_gemm_body(
    float acc[16][4], uint32_t smb, int tid,
    const __nv_bfloat16* gwh, const __nv_bfloat16* gwl,
    const __nv_bfloat16* xh, const __nv_bfloat16* xl,
    int m0, int s0)
{
    int w = tid >> 5, lane = tid & 31;
    int rsel = lane & 15, csel = lane >> 4;

    conv_issue(smb, tid, 0, gwh, gwl, xh, xl, m0, s0);
    cpa_commit();

    for (int kc = 0; kc < 16; kc++) {
        cpa_wait_all();
        __syncthreads();
        if (kc < 15) {
            conv_issue(smb + ((kc + 1) & 1) * STG, tid, kc + 1, gwh, gwl, xh, xl, m0, s0);
            cpa_commit();
        }
        uint32_t base = smb + (kc & 1) * STG;
        uint32_t aW  = base + (16 * w + rsel) * 48 + csel * 16;
        uint32_t aWl = aW + WL_OFF;
        uint32_t aX  = base + XH_OFF + rsel * 272 + csel * 16;
        uint32_t aXl = aX + (XL_OFF - XH_OFF);

        uint32_t awh[4], awl[4];
        ldsm4(awh, aW);
        ldsm4(awl, aWl);
#pragma unroll
        for (int nt = 0; nt < 8; nt++) {
            uint32_t bxh[4], bxl[4];
            ldsm4t(bxh, aX + nt * 32);
            ldsm4t(bxl, aXl + nt * 32);
            float* oA = acc[2 * nt];
            float* oB = acc[2 * nt + 1];
            mma16816(oA, awh, bxh[0], bxh[1]);
            mma16816(oA, awh, bxl[0], bxl[1]);
            mma16816(oA, awl, bxh[0], bxh[1]);
            mma16816(oB, awh, bxh[2], bxh[3]);
            mma16816(oB, awh, bxl[2], bxl[3]);
            mma16816(oB, awl, bxh[2], bxh[3]);
        }
    }
}

// ---- Q/K/V conv: bias + split -> bf16 hi/lo outputs ----
__global__ __launch_bounds__(256) void qkv_mma_kernel(
    const float* __restrict__ bq, const float* __restrict__ bk, const float* __restrict__ bv)
{
    __shared__ __align__(16) char smem[2 * STG];
    int z = blockIdx.z, b = z / 3, which = z % 3;
    const __nv_bfloat16* gwh = g_wh + (size_t)which * 65536;
    const __nv_bfloat16* gwl = g_wl + (size_t)which * 65536;
    const float* bias = (which == 0) ? bq : (which == 1) ? bk : bv;
    __nv_bfloat16* oh = (which == 0) ? g_qh : (which == 1) ? g_kh : g_vh;
    __nv_bfloat16* ol = (which == 0) ? g_ql : (which == 1) ? g_kl : g_vl;
    int m0 = blockIdx.y * 128, s0 = blockIdx.x * 128;
    int tid = threadIdx.x;
    size_t ob = (size_t)b * CH * SP;
    const __nv_bfloat16* xh = g_xh + ob;
    const __nv_bfloat16* xl = g_xl + ob;

    float acc[16][4];
#pragma unroll
    for (int i = 0; i < 16; i++)
#pragma unroll
        for (int j = 0; j < 4; j++) acc[i][j] = 0.0f;

    conv_gemm_body(acc, sm_u32(smem), tid, gwh, gwl, xh, xl, m0, s0);

    int w = tid >> 5, lane = tid & 31;
    int r0 = 16 * w + (lane >> 2), c2 = (lane & 3) * 2;
    float b0 = bias[m0 + r0], b1 = bias[m0 + r0 + 8];
    size_t ro0 = ob + (size_t)(m0 + r0) * SP;
    size_t ro1 = ob + (size_t)(m0 + r0 + 8) * SP;
#pragma unroll
    for (int nt = 0; nt < 8; nt++) {
        int c = s0 + nt * 16 + c2;
        uint32_t hh, ll;
        split2(acc[2 * nt][0] + b0, acc[2 * nt][1] + b0, hh, ll);
        *(uint32_t*)&oh[ro0 + c] = hh;  *(uint32_t*)&ol[ro0 + c] = ll;
        split2(acc[2 * nt][2] + b1, acc[2 * nt][3] + b1, hh, ll);
        *(uint32_t*)&oh[ro1 + c] = hh;  *(uint32_t*)&ol[ro1 + c] = ll;
        split2(acc[2 * nt + 1][0] + b0, acc[2 * nt + 1][1] + b0, hh, ll);
        *(uint32_t*)&oh[ro0 + c + 8] = hh;  *(uint32_t*)&ol[ro0 + c + 8] = ll;
        split2(acc[2 * nt + 1][2] + b1, acc[2 * nt + 1][3] + b1, hh, ll);
        *(uint32_t*)&oh[ro1 + c + 8] = hh;  *(uint32_t*)&ol[ro1 + c + 8] = ll;
    }
}

// ---- output conv: bias + residual -> fp32 out ----
__global__ __launch_bounds__(256) void out_mma_kernel(
    const float* __restrict__ x, const float* __restrict__ bu, float* __restrict__ out)
{
    __shared__ __align__(16) char smem[2 * STG];
    int b = blockIdx.z;
    const __nv_bfloat16* gwh = g_wh + (size_t)3 * 65536;
    const __nv_bfloat16* gwl = g_wl + (size_t)3 * 65536;
    int m0 = blockIdx.y * 128, s0 = blockIdx.x * 128;
    int tid = threadIdx.x;
    size_t ob = (size_t)b * CH * SP;
    const __nv_bfloat16* ah = g_ah + ob;
    const __nv_bfloat16* al = g_al + ob;

    float acc[16][4];
#pragma unroll
    for (int i = 0; i < 16; i++)
#pragma unroll
        for (int j = 0; j < 4; j++) acc[i][j] = 0.0f;

    conv_gemm_body(acc, sm_u32(smem), tid, gwh, gwl, ah, al, m0, s0);

    int w = tid >> 5, lane = tid & 31;
    int r0 = 16 * w + (lane >> 2), c2 = (lane & 3) * 2;
    float b0 = bu[m0 + r0], b1 = bu[m0 + r0 + 8];
    size_t ro0 = ob + (size_t)(m0 + r0) * SP;
    size_t ro1 = ob + (size_t)(m0 + r0 + 8) * SP;
#pragma unroll
    for (int nt = 0; nt < 8; nt++) {
        int c = s0 + nt * 16 + c2;
        float2 x00 = *(const float2*)&x[ro0 + c];
        float2 x10 = *(const float2*)&x[ro1 + c];
        float2 x01 = *(const float2*)&x[ro0 + c + 8];
        float2 x11 = *(const float2*)&x[ro1 + c + 8];
        float2 v;
        v.x = acc[2 * nt][0] + b0 + x00.x;  v.y = acc[2 * nt][1] + b0 + x00.y;
        *(float2*)&out[ro0 + c] = v;
        v.x = acc[2 * nt][2] + b1 + x10.x;  v.y = acc[2 * nt][3] + b1 + x10.y;
        *(float2*)&out[ro1 + c] = v;
        v.x = acc[2 * nt + 1][0] + b0 + x01.x;  v.y = acc[2 * nt + 1][1] + b0 + x01.y;
        *(float2*)&out[ro0 + c + 8] = v;
        v.x = acc[2 * nt + 1][2] + b1 + x11.x;  v.y = acc[2 * nt + 1][3] + b1 + x11.y;
        *(float2*)&out[ro1 + c + 8] = v;
    }
}

// ---------------------------------------------------------------------------
// Flash attention (R4 kernel, best). Epilogue writes bf16 hi/lo to g_ah/g_al.
// ---------------------------------------------------------------------------
#define SQ 264
#define ATTN_SMEM ((2 * 128 * SQ + 4 * 32 * SQ) * 2)

__global__ __launch_bounds__(256, 1) void attn_kernel()
{
    extern __shared__ __nv_bfloat16 sm[];
    __nv_bfloat16* Qh = sm;
    __nv_bfloat16* Ql = Qh + 128 * SQ;
    __nv_bfloat16* Kh = Ql + 128 * SQ;
    __nv_bfloat16* Kl = Kh + 32 * SQ;
    __nv_bfloat16* Vh = Kl + 32 * SQ;
    __nv_bfloat16* Vl = Vh + 32 * SQ;

    int b = blockIdx.y;
    int n0 = blockIdx.x * 128;
    int tid = threadIdx.x;
    int w = tid >> 5, lane = tid & 31;

    size_t base = (size_t)b * CH * SP;
    const uint4* Qgh = (const uint4*)(g_qh + base);
    const uint4* Qgl = (const uint4*)(g_ql + base);
    const uint4* Kgh = (const uint4*)(g_kh + base);
    const uint4* Kgl = (const uint4*)(g_kl + base);
    const uint4* Vgh = (const uint4*)(g_vh + base);
    const uint4* Vgl = (const uint4*)(g_vl + base);

    int lr0 = tid >> 3, lc0 = (tid & 7) * 4;
    uint32_t sKh = sm_u32(Kh), sKl = sm_u32(Kl), sVh = sm_u32(Vh), sVl = sm_u32(Vl);

    {
        size_t g = (size_t)lr0 * 32 + lc0;
        uint32_t s = (uint32_t)(lr0 * 33 + lc0) * 16;
#pragma unroll
        for (int j = 0; j < 4; j++) {
            cpa16(sKh + s + j * 16, Kgh + g + j);
            cpa16(sKl + s + j * 16, Kgl + g + j);
        }
        cpa_commit();
    }

    for (int idx = tid; idx < 128 * 32; idx += 256) {
        int r = idx >> 5, c = idx & 31;
        ((uint4*)Qh)[r * 33 + c] = Qgh[(size_t)(n0 + r) * 32 + c];
        ((uint4*)Ql)[r * 33 + c] = Qgl[(size_t)(n0 + r) * 32 + c];
    }

    int rsel = lane & 15, csel = lane >> 4;
    uint32_t aQh = sm_u32(Qh + (w * 16 + rsel) * SQ + csel * 8);
    uint32_t aQl = aQh + 128 * SQ * 2;
    uint32_t aKh = sm_u32(Kh + rsel * SQ + csel * 8);
    uint32_t aKl = aKh + 32 * SQ * 2;
    uint32_t aVh = sm_u32(Vh + rsel * SQ + csel * 8);
    uint32_t aVl = aVh + 32 * SQ * 2;

    float o[32][4];
#pragma unroll
    for (int i = 0; i < 32; i++)
#pragma unroll
        for (int j = 0; j < 4; j++) o[i][j] = 0.0f;
    float m0r = -1e30f, m1r = -1e30f, l0r = 0.0f, l1r = 0.0f;

    for (int mt = 0; mt < 128; mt++) {
        cpa_wait_all();
        __syncthreads();

        {
            size_t g = (size_t)(mt * 32 + lr0) * 32 + lc0;
            uint32_t s = (uint32_t)(lr0 * 33 + lc0) * 16;
#pragma unroll
            for (int j = 0; j < 4; j++) {
                cpa16(sVh + s + j * 16, Vgh + g + j);
                cpa16(sVl + s + j * 16, Vgl + g + j);
            }
            cpa_commit();
        }

        float s[4][4];
#pragma unroll
        for (int i = 0; i < 4; i++)
#pragma unroll
            for (int j = 0; j < 4; j++) s[i][j] = 0.0f;

#pragma unroll
        for (int kc = 0; kc < 16; kc++) {
            uint32_t ah[4], al[4];
            ldsm4(ah, aQh + kc * 32);
            ldsm4(al, aQl + kc * 32);
#pragma unroll
            for (int np = 0; np < 2; np++) {
                uint32_t bh[4], bl[4];
                ldsm4(bh, aKh + np * (16 * SQ * 2) + kc * 32);
                ldsm4(bl, aKl + np * (16 * SQ * 2) + kc * 32);
                float* sA = s[2 * np];
                float* sB = s[2 * np + 1];
                mma16816(sA, ah, bh[0], bh[2]);
                mma16816(sA, ah, bl[0], bl[2]);
                mma16816(sA, al, bh[0], bh[2]);
                mma16816(sB, ah, bh[1], bh[3]);
                mma16816(sB, ah, bl[1], bl[3]);
                mma16816(sB, al, bh[1], bh[3]);
            }
        }

        cpa_wait_all();
        __syncthreads();

        if (mt + 1 < 128) {
            size_t g = (size_t)((mt + 1) * 32 + lr0) * 32 + lc0;
            uint32_t s2 = (uint32_t)(lr0 * 33 + lc0) * 16;
#pragma unroll
            for (int j = 0; j < 4; j++) {
                cpa16(sKh + s2 + j * 16, Kgh + g + j);
                cpa16(sKl + s2 + j * 16, Kgl + g + j);
            }
            cpa_commit();
        }

        float mx0 = s[0][0], mx1 = s[0][2];
#pragma unroll
        for (int nt = 0; nt < 4; nt++) {
            mx0 = fmaxf(mx0, fmaxf(s[nt][0], s[nt][1]));
            mx1 = fmaxf(mx1, fmaxf(s[nt][2], s[nt][3]));
        }
        mx0 = fmaxf(mx0, __shfl_xor_sync(0xffffffffu, mx0, 1));
        mx0 = fmaxf(mx0, __shfl_xor_sync(0xffffffffu, mx0, 2));
        mx1 = fmaxf(mx1, __shfl_xor_sync(0xffffffffu, mx1, 1));
        mx1 = fmaxf(mx1, __shfl_xor_sync(0xffffffffu, mx1, 2));

        float mn0 = fmaxf(m0r, mx0), mn1 = fmaxf(m1r, mx1);
        float sc0 = __expf(m0r - mn0), sc1 = __expf(m1r - mn1);
        m0r = mn0; m1r = mn1;

        float rs0 = 0.0f, rs1 = 0.0f;
#pragma unroll
        for (int nt = 0; nt < 4; nt++) {
            s[nt][0] = __expf(s[nt][0] - mn0);
            s[nt][1] = __expf(s[nt][1] - mn0);
            s[nt][2] = __expf(s[nt][2] - mn1);
            s[nt][3] = __expf(s[nt][3] - mn1);
            rs0 += s[nt][0] + s[nt][1];
            rs1 += s[nt][2] + s[nt][3];
        }
        rs0 += __shfl_xor_sync(0xffffffffu, rs0, 1);
        rs0 += __shfl_xor_sync(0xffffffffu, rs0, 2);
        rs1 += __shfl_xor_sync(0xffffffffu, rs1, 1);
        rs1 += __shfl_xor_sync(0xffffffffu, rs1, 2);
        l0r = l0r * sc0 + rs0;
        l1r = l1r * sc1 + rs1;

#pragma unroll
        for (int nt = 0; nt < 32; nt++) {
            o[nt][0] *= sc0; o[nt][1] *= sc0;
            o[nt][2] *= sc1; o[nt][3] *= sc1;
        }

        uint32_t ph[2][4], pl[2][4];
#pragma unroll
        for (int kc = 0; kc < 2; kc++) {
            int nt0 = 2 * kc, nt1 = 2 * kc + 1;
            split2(s[nt0][0], s[nt0][1], ph[kc][0], pl[kc][0]);
            split2(s[nt0][2], s[nt0][3], ph[kc][1], pl[kc][1]);
            split2(s[nt1][0], s[nt1][1], ph[kc][2], pl[kc][2]);
            split2(s[nt1][2], s[nt1][3], ph[kc][3], pl[kc][3]);
        }

#pragma unroll
        for (int kc = 0; kc < 2; kc++) {
#pragma unroll
            for (int ct = 0; ct < 16; ct++) {
                uint32_t vh[4], vl[4];
                ldsm4t(vh, aVh + kc * (16 * SQ * 2) + ct * 32);
                ldsm4t(vl, aVl + kc * (16 * SQ * 2) + ct * 32);
                float* oA = o[2 * ct];
                float* oB = o[2 * ct + 1];
                mma16816(oA, ph[kc], vh[0], vh[1]);
                mma16816(oA, ph[kc], vl[0], vl[1]);
                mma16816(oA, pl[kc], vh[0], vh[1]);
                mma16816(oB, ph[kc], vh[2], vh[3]);
                mma16816(oB, ph[kc], vl[2], vl[3]);
                mma16816(oB, pl[kc], vh[2], vh[3]);
            }
        }
    }

    // epilogue: normalize and store bf16 hi/lo rows to g_ah/g_al
    float inv0 = 1.0f / l0r, inv1 = 1.0f / l1r;
    int r0 = n0 + w * 16 + (lane >> 2);
    int r1 = r0 + 8;
    int cb = (lane & 3) * 2;
#pragma unroll
    for (int nt = 0; nt < 32; nt++) {
        int c = nt * 8 + cb;
        uint32_t hh, ll;
        split2(o[nt][0] * inv0, o[nt][1] * inv0, hh, ll);
        *(uint32_t*)&g_ah[base + (size_t)r0 * 256 + c] = hh;
        *(uint32_t*)&g_al[base + (size_t)r0 * 256 + c] = ll;
        split2(o[nt][2] * inv1, o[nt][3] * inv1, hh, ll);
        *(uint32_t*)&g_ah[base + (size_t)r1 * 256 + c] = hh;
        *(uint32_t*)&g_al[base + (size_t)r1 * 256 + c] = ll;
    }
}

// ---------------------------------------------------------------------------
extern "C" void kernel_launch(void* const* d_in, const int* in_sizes, int n_in,
                              void* d_out, int out_size)
{
    (void)in_sizes; (void)n_in; (void)out_size;
    const float* x  = (const float*)d_in[0];
    const float* Wq = (const float*)d_in[1];
    const float* bq = (const float*)d_in[2];
    const float* Wk = (const float*)d_in[3];
    const float* bk = (const float*)d_in[4];
    const float* Wv = (const float*)d_in[5];
    const float* bv = (const float*)d_in[6];
    const float* Wu = (const float*)d_in[7];
    const float* bu = (const float*)d_in[8];
    float* out = (float*)d_out;

    cudaFuncSetAttribute(attn_kernel, cudaFuncAttributeMaxDynamicSharedMemorySize, ATTN_SMEM);

    splitx_kernel<<<4096, 256>>>(x);
    splitw_kernel<<<256, 256>>>(Wq, Wk, Wv, Wu);
    qkv_mma_kernel<<<dim3(32, 2, 12), 256>>>(bq, bk, bv);
    attn_kernel<<<dim3(32, 4), 256, ATTN_SMEM>>>();
    out_mma_kernel<<<dim3(32, 2, 4), 256>>>(x, bu, out);
}